// round 1
// baseline (speedup 1.0000x reference)
#include <cuda_runtime.h>
#include <cuda_bf16.h>

// Problem constants
#define BS      4
#define SEQ     2048
#define DMODEL  768
#define NHEAD   12
#define DHEAD   64
#define MROWS   (BS * SEQ)          // 8192

// ---------------- scratch (no cudaMalloc allowed) ----------------
__device__ float g_Qp[MROWS * DMODEL];
__device__ float g_Kp[MROWS * DMODEL];
__device__ float g_Vp[MROWS * DMODEL];

// =================================================================
// Projection GEMM: Y[M,N] = X[M,K] @ W[N,K]^T + bias[N]
// M=8192, N=768, K=768. Tile 128x128x16, 256 threads, 8x8 microtile.
// =================================================================
__global__ __launch_bounds__(256) void proj_gemm(
    const float* __restrict__ X, const float* __restrict__ W,
    const float* __restrict__ bias, float* __restrict__ Y)
{
    const int K = DMODEL, N = DMODEL;
    __shared__ float As[16 * 128];
    __shared__ float Bs[16 * 128];

    const int tid = threadIdx.x;
    const int tx = tid & 15;        // 0..15 -> n
    const int ty = tid >> 4;        // 0..15 -> m
    const int m0 = blockIdx.y * 128;
    const int n0 = blockIdx.x * 128;

    float acc[8][8];
#pragma unroll
    for (int i = 0; i < 8; i++)
#pragma unroll
        for (int j = 0; j < 8; j++) acc[i][j] = 0.0f;

    for (int k0 = 0; k0 < K; k0 += 16) {
        // cooperative load: 128x16 of X and W (K-contig), store k-major
#pragma unroll
        for (int i = 0; i < 2; i++) {
            int f   = tid * 2 + i;          // 0..511 float4 slots
            int row = f >> 2;               // 0..127
            int c4  = (f & 3) * 4;          // 0,4,8,12
            float4 av = *(const float4*)&X[(size_t)(m0 + row) * K + k0 + c4];
            As[(c4 + 0) * 128 + row] = av.x;
            As[(c4 + 1) * 128 + row] = av.y;
            As[(c4 + 2) * 128 + row] = av.z;
            As[(c4 + 3) * 128 + row] = av.w;
            float4 bv = *(const float4*)&W[(size_t)(n0 + row) * K + k0 + c4];
            Bs[(c4 + 0) * 128 + row] = bv.x;
            Bs[(c4 + 1) * 128 + row] = bv.y;
            Bs[(c4 + 2) * 128 + row] = bv.z;
            Bs[(c4 + 3) * 128 + row] = bv.w;
        }
        __syncthreads();

#pragma unroll
        for (int k = 0; k < 16; k++) {
            float af[8], bf[8];
            *(float4*)&af[0] = *(const float4*)&As[k * 128 + ty * 8];
            *(float4*)&af[4] = *(const float4*)&As[k * 128 + ty * 8 + 4];
            *(float4*)&bf[0] = *(const float4*)&Bs[k * 128 + tx * 8];
            *(float4*)&bf[4] = *(const float4*)&Bs[k * 128 + tx * 8 + 4];
#pragma unroll
            for (int i = 0; i < 8; i++)
#pragma unroll
                for (int j = 0; j < 8; j++)
                    acc[i][j] = fmaf(af[i], bf[j], acc[i][j]);
        }
        __syncthreads();
    }

    float bv[8];
    *(float4*)&bv[0] = *(const float4*)&bias[n0 + tx * 8];
    *(float4*)&bv[4] = *(const float4*)&bias[n0 + tx * 8 + 4];
#pragma unroll
    for (int i = 0; i < 8; i++) {
        float4 o0 = make_float4(acc[i][0] + bv[0], acc[i][1] + bv[1],
                                acc[i][2] + bv[2], acc[i][3] + bv[3]);
        float4 o1 = make_float4(acc[i][4] + bv[4], acc[i][5] + bv[5],
                                acc[i][6] + bv[6], acc[i][7] + bv[7]);
        size_t base = (size_t)(m0 + ty * 8 + i) * N + n0 + tx * 8;
        *(float4*)&Y[base]     = o0;
        *(float4*)&Y[base + 4] = o1;
    }
}

// =================================================================
// Flash attention (no scale, no mask): per CTA one (b, h, 64-q tile)
// 128 threads: tx=tid&7 (8 keys / 8 d-cols), ty=tid>>3 (4 q-rows)
// =================================================================
#define FA_LD 68                    // padded row stride (floats), 16B aligned
#define FA_SMEM (4 * 64 * FA_LD * 4)

__global__ __launch_bounds__(128) void flash_attn(
    const float* __restrict__ Qp, const float* __restrict__ Kp,
    const float* __restrict__ Vp, float* __restrict__ Out)
{
    extern __shared__ float sm[];
    float* Qs  = sm;                    // [64][FA_LD]  row-major (q, d)
    float* Kst = sm + 64 * FA_LD;       // [64][FA_LD]  d-major  (d, key)
    float* Vs  = sm + 2 * 64 * FA_LD;   // [64][FA_LD]  row-major (key, d)
    float* Ps  = sm + 3 * 64 * FA_LD;   // [64][FA_LD]  row-major (q, key)

    const int qt = blockIdx.x;          // 0..31
    const int h  = blockIdx.y;          // 0..11
    const int b  = blockIdx.z;          // 0..3

    const int tid   = threadIdx.x;
    const int tx    = tid & 7;          // 8 lanes per row group
    const int ty    = tid >> 3;         // 16 groups
    const int qrow0 = ty * 4;
    const int col0  = tx * 8;           // key offset in S phase / d offset in PV

    const size_t head_off = (size_t)h * DHEAD;

    // ---- load Q tile once ----
    {
        int r = tid >> 1, half = tid & 1;
        const float4* src = (const float4*)&Qp[((size_t)(b * SEQ + qt * 64 + r)) * DMODEL
                                               + head_off + half * 32];
        float4* dst = (float4*)&Qs[r * FA_LD + half * 32];
#pragma unroll
        for (int c = 0; c < 8; c++) dst[c] = src[c];
    }

    float m[4], l[4], acc[4][8];
#pragma unroll
    for (int i = 0; i < 4; i++) {
        m[i] = -1e30f;
        l[i] = 0.0f;
#pragma unroll
        for (int d = 0; d < 8; d++) acc[i][d] = 0.0f;
    }
    __syncthreads();

    for (int kt = 0; kt < SEQ / 64; kt++) {
        // ---- load K tile (transposed to d-major) and V tile ----
        {
            int r = tid >> 1, half = tid & 1;
            size_t grow = ((size_t)(b * SEQ + kt * 64 + r)) * DMODEL + head_off + half * 32;
            const float4* ksrc = (const float4*)&Kp[grow];
#pragma unroll
            for (int c = 0; c < 8; c++) {
                float4 kv = ksrc[c];
                int d = half * 32 + c * 4;
                Kst[(d + 0) * FA_LD + r] = kv.x;
                Kst[(d + 1) * FA_LD + r] = kv.y;
                Kst[(d + 2) * FA_LD + r] = kv.z;
                Kst[(d + 3) * FA_LD + r] = kv.w;
            }
            const float4* vsrc = (const float4*)&Vp[grow];
            float4* vdst = (float4*)&Vs[r * FA_LD + half * 32];
#pragma unroll
            for (int c = 0; c < 8; c++) vdst[c] = vsrc[c];
        }
        __syncthreads();

        // ---- S = Q . K^T  (4 rows x 8 keys per thread) ----
        float s[4][8];
#pragma unroll
        for (int i = 0; i < 4; i++)
#pragma unroll
            for (int j = 0; j < 8; j++) s[i][j] = 0.0f;

#pragma unroll 1
        for (int k4 = 0; k4 < DHEAD; k4 += 4) {
            float qa[4][4];
#pragma unroll
            for (int i = 0; i < 4; i++)
                *(float4*)qa[i] = *(const float4*)&Qs[(qrow0 + i) * FA_LD + k4];
#pragma unroll
            for (int e = 0; e < 4; e++) {
                float kf[8];
                *(float4*)&kf[0] = *(const float4*)&Kst[(k4 + e) * FA_LD + col0];
                *(float4*)&kf[4] = *(const float4*)&Kst[(k4 + e) * FA_LD + col0 + 4];
#pragma unroll
                for (int i = 0; i < 4; i++) {
                    float q = qa[i][e];
#pragma unroll
                    for (int j = 0; j < 8; j++)
                        s[i][j] = fmaf(q, kf[j], s[i][j]);
                }
            }
        }

        // ---- online softmax update ----
#pragma unroll
        for (int i = 0; i < 4; i++) {
            float mt = s[i][0];
#pragma unroll
            for (int j = 1; j < 8; j++) mt = fmaxf(mt, s[i][j]);
            mt = fmaxf(mt, __shfl_xor_sync(0xffffffffu, mt, 1));
            mt = fmaxf(mt, __shfl_xor_sync(0xffffffffu, mt, 2));
            mt = fmaxf(mt, __shfl_xor_sync(0xffffffffu, mt, 4));
            float mnew = fmaxf(m[i], mt);
            float corr = __expf(m[i] - mnew);
            float p[8];
            float ls = 0.0f;
#pragma unroll
            for (int j = 0; j < 8; j++) {
                p[j] = __expf(s[i][j] - mnew);
                ls += p[j];
            }
            ls += __shfl_xor_sync(0xffffffffu, ls, 1);
            ls += __shfl_xor_sync(0xffffffffu, ls, 2);
            ls += __shfl_xor_sync(0xffffffffu, ls, 4);
            l[i] = l[i] * corr + ls;
            m[i] = mnew;
#pragma unroll
            for (int d = 0; d < 8; d++) acc[i][d] *= corr;
            *(float4*)&Ps[(qrow0 + i) * FA_LD + col0]     = *(float4*)&p[0];
            *(float4*)&Ps[(qrow0 + i) * FA_LD + col0 + 4] = *(float4*)&p[4];
        }
        __syncthreads();

        // ---- acc += P . V  (4 rows x 8 d-cols per thread) ----
#pragma unroll 1
        for (int j4 = 0; j4 < 64; j4 += 4) {
            float pa[4][4];
#pragma unroll
            for (int i = 0; i < 4; i++)
                *(float4*)pa[i] = *(const float4*)&Ps[(qrow0 + i) * FA_LD + j4];
#pragma unroll
            for (int e = 0; e < 4; e++) {
                float vf[8];
                *(float4*)&vf[0] = *(const float4*)&Vs[(j4 + e) * FA_LD + col0];
                *(float4*)&vf[4] = *(const float4*)&Vs[(j4 + e) * FA_LD + col0 + 4];
#pragma unroll
                for (int i = 0; i < 4; i++) {
                    float pv = pa[i][e];
#pragma unroll
                    for (int d = 0; d < 8; d++)
                        acc[i][d] = fmaf(pv, vf[d], acc[i][d]);
                }
            }
        }
        __syncthreads();   // protect Kst/Vs/Ps before next tile's loads
    }

    // ---- write output (merged heads layout [b, s, h*64+d]) ----
#pragma unroll
    for (int i = 0; i < 4; i++) {
        float inv = 1.0f / l[i];
        float4 o0 = make_float4(acc[i][0] * inv, acc[i][1] * inv,
                                acc[i][2] * inv, acc[i][3] * inv);
        float4 o1 = make_float4(acc[i][4] * inv, acc[i][5] * inv,
                                acc[i][6] * inv, acc[i][7] * inv);
        size_t base = ((size_t)(b * SEQ + qt * 64 + qrow0 + i)) * DMODEL
                      + head_off + col0;
        *(float4*)&Out[base]     = o0;
        *(float4*)&Out[base + 4] = o1;
    }
}

// =================================================================
extern "C" void kernel_launch(void* const* d_in, const int* in_sizes, int n_in,
                              void* d_out, int out_size)
{
    const float* q  = (const float*)d_in[0];
    const float* k  = (const float*)d_in[1];
    const float* v  = (const float*)d_in[2];
    const float* Wq = (const float*)d_in[3];
    const float* bq = (const float*)d_in[4];
    const float* Wk = (const float*)d_in[5];
    const float* bk = (const float*)d_in[6];
    const float* Wv = (const float*)d_in[7];
    const float* bv = (const float*)d_in[8];
    float* out = (float*)d_out;

    float *Qp, *Kp, *Vp;
    cudaGetSymbolAddress((void**)&Qp, g_Qp);
    cudaGetSymbolAddress((void**)&Kp, g_Kp);
    cudaGetSymbolAddress((void**)&Vp, g_Vp);

    dim3 pgrid(DMODEL / 128, MROWS / 128);   // (6, 64)
    proj_gemm<<<pgrid, 256>>>(q, Wq, bq, Qp);
    proj_gemm<<<pgrid, 256>>>(k, Wk, bk, Kp);
    proj_gemm<<<pgrid, 256>>>(v, Wv, bv, Vp);

    cudaFuncSetAttribute(flash_attn, cudaFuncAttributeMaxDynamicSharedMemorySize,
                         FA_SMEM);
    dim3 agrid(SEQ / 64, NHEAD, BS);         // (32, 12, 4)
    flash_attn<<<agrid, 128, FA_SMEM>>>(Qp, Kp, Vp, out);
}

// round 3
// speedup vs baseline: 1.5775x; 1.5775x over previous
#include <cuda_runtime.h>
#include <cuda_bf16.h>
#include <cstdint>

// Problem constants
#define BS      4
#define SEQ     2048
#define DMODEL  768
#define NHEAD   12
#define DHEAD   64
#define MROWS   (BS * SEQ)          // 8192

// ---------------- scratch (no cudaMalloc allowed) ----------------
__device__ float g_Qp[MROWS * DMODEL];
__device__ float g_Kp[MROWS * DMODEL];
__device__ float g_Vp[MROWS * DMODEL];
__device__ __nv_bfloat16 g_Ah[3 * MROWS * DMODEL];   // q,k,v inputs hi
__device__ __nv_bfloat16 g_Al[3 * MROWS * DMODEL];   // q,k,v inputs lo
__device__ __nv_bfloat16 g_Wh[3 * DMODEL * DMODEL];  // Wq,Wk,Wv hi
__device__ __nv_bfloat16 g_Wl[3 * DMODEL * DMODEL];  // Wq,Wk,Wv lo

// =================================================================
// fp32 -> (hi, lo) bf16 split
// =================================================================
__global__ __launch_bounds__(256) void split_bf16(
    const float* __restrict__ src, __nv_bfloat16* __restrict__ hi,
    __nv_bfloat16* __restrict__ lo, int n4)
{
    int i = blockIdx.x * blockDim.x + threadIdx.x;
    if (i >= n4) return;
    float4 x = ((const float4*)src)[i];
    __nv_bfloat16 h0 = __float2bfloat16(x.x);
    __nv_bfloat16 h1 = __float2bfloat16(x.y);
    __nv_bfloat16 h2 = __float2bfloat16(x.z);
    __nv_bfloat16 h3 = __float2bfloat16(x.w);
    __nv_bfloat16 l0 = __float2bfloat16(x.x - __bfloat162float(h0));
    __nv_bfloat16 l1 = __float2bfloat16(x.y - __bfloat162float(h1));
    __nv_bfloat16 l2 = __float2bfloat16(x.z - __bfloat162float(h2));
    __nv_bfloat16 l3 = __float2bfloat16(x.w - __bfloat162float(h3));
    __nv_bfloat162* hp = (__nv_bfloat162*)hi;
    __nv_bfloat162* lp = (__nv_bfloat162*)lo;
    hp[2 * i]     = __halves2bfloat162(h0, h1);
    hp[2 * i + 1] = __halves2bfloat162(h2, h3);
    lp[2 * i]     = __halves2bfloat162(l0, l1);
    lp[2 * i + 1] = __halves2bfloat162(l2, l3);
}

// =================================================================
// mma.sync helper (sm_80+ family-common HMMA, bf16 -> f32)
// =================================================================
__device__ __forceinline__ void mma16816(float* c, const uint32_t* a, const uint32_t* b)
{
    asm volatile(
        "mma.sync.aligned.m16n8k16.row.col.f32.bf16.bf16.f32 "
        "{%0,%1,%2,%3},{%4,%5,%6,%7},{%8,%9},{%0,%1,%2,%3};"
        : "+f"(c[0]), "+f"(c[1]), "+f"(c[2]), "+f"(c[3])
        : "r"(a[0]), "r"(a[1]), "r"(a[2]), "r"(a[3]), "r"(b[0]), "r"(b[1]));
}

// =================================================================
// Projection GEMM via mma.sync, split-bf16 3-term: Y = X @ W^T + b
// CTA 128x128, K-chunk 64, 8 warps (2M x 4N), warp tile 64x32.
// smem tiles: rows x 72 halves (144 B row stride, LDS conflict-free)
// =================================================================
#define PJ_STRIDE_B 144                      // 72 halves
#define PJ_TILE_B   (128 * PJ_STRIDE_B)      // 18432
#define PJ_SMEM     (4 * PJ_TILE_B)          // 73728

__global__ __launch_bounds__(256) void proj_mma(
    const __nv_bfloat16* __restrict__ Xh, const __nv_bfloat16* __restrict__ Xl,
    const __nv_bfloat16* __restrict__ Wh, const __nv_bfloat16* __restrict__ Wl,
    const float* __restrict__ bias, float* __restrict__ Y)
{
    extern __shared__ __align__(16) char sm[];
    char* smAh = sm;
    char* smAl = sm + PJ_TILE_B;
    char* smBh = sm + 2 * PJ_TILE_B;
    char* smBl = sm + 3 * PJ_TILE_B;

    const int K = DMODEL;
    const int tid  = threadIdx.x;
    const int wid  = tid >> 5;
    const int lane = tid & 31;
    const int m0 = blockIdx.y * 128;
    const int n0 = blockIdx.x * 128;
    const int wm = (wid >> 2) * 64;      // warp M offset (0 or 64)
    const int wn = (wid & 3) * 32;       // warp N offset
    const int qr = lane >> 2;            // quad row 0..7
    const int qc = (lane & 3) * 2;       // quad col pair base

    float acc[4][4][4];
#pragma unroll
    for (int i = 0; i < 4; i++)
#pragma unroll
        for (int j = 0; j < 4; j++)
#pragma unroll
            for (int r = 0; r < 4; r++) acc[i][j][r] = 0.0f;

    for (int c = 0; c < 12; c++) {
        const int k0 = c * 64;
        // ---- cooperative loads: 4 tiles of 128 rows x 64 halves ----
#pragma unroll
        for (int it = 0; it < 4; it++) {
            int idx = it * 256 + tid;        // 0..1023
            int row = idx >> 3;
            int c8  = idx & 7;
            size_t goff = (size_t)(m0 + row) * K + k0 + c8 * 8;
            size_t woff = (size_t)(n0 + row) * K + k0 + c8 * 8;
            uint32_t soff = row * PJ_STRIDE_B + c8 * 16;
            *(uint4*)(smAh + soff) = *(const uint4*)&Xh[goff];
            *(uint4*)(smAl + soff) = *(const uint4*)&Xl[goff];
            *(uint4*)(smBh + soff) = *(const uint4*)&Wh[woff];
            *(uint4*)(smBl + soff) = *(const uint4*)&Wl[woff];
        }
        __syncthreads();

#pragma unroll
        for (int ks = 0; ks < 4; ks++) {
            const int kb = ks * 16 + qc;     // half-index within chunk
            uint32_t ah[4][4], al[4][4], bh[4][2], bl[4][2];
#pragma unroll
            for (int i = 0; i < 4; i++) {
                int r0 = wm + i * 16 + qr;
                uint32_t o00 = r0 * PJ_STRIDE_B + kb * 2;
                uint32_t o10 = (r0 + 8) * PJ_STRIDE_B + kb * 2;
                ah[i][0] = *(const uint32_t*)(smAh + o00);
                ah[i][1] = *(const uint32_t*)(smAh + o10);
                ah[i][2] = *(const uint32_t*)(smAh + o00 + 16);
                ah[i][3] = *(const uint32_t*)(smAh + o10 + 16);
                al[i][0] = *(const uint32_t*)(smAl + o00);
                al[i][1] = *(const uint32_t*)(smAl + o10);
                al[i][2] = *(const uint32_t*)(smAl + o00 + 16);
                al[i][3] = *(const uint32_t*)(smAl + o10 + 16);
            }
#pragma unroll
            for (int j = 0; j < 4; j++) {
                int r0 = wn + j * 8 + qr;    // n-row
                uint32_t o0 = r0 * PJ_STRIDE_B + kb * 2;
                bh[j][0] = *(const uint32_t*)(smBh + o0);
                bh[j][1] = *(const uint32_t*)(smBh + o0 + 16);
                bl[j][0] = *(const uint32_t*)(smBl + o0);
                bl[j][1] = *(const uint32_t*)(smBl + o0 + 16);
            }
#pragma unroll
            for (int i = 0; i < 4; i++)
#pragma unroll
                for (int j = 0; j < 4; j++) {
                    mma16816(acc[i][j], ah[i], bh[j]);
                    mma16816(acc[i][j], ah[i], bl[j]);
                    mma16816(acc[i][j], al[i], bh[j]);
                }
        }
        __syncthreads();
    }

    // ---- epilogue: add bias, write fp32 ----
#pragma unroll
    for (int j = 0; j < 4; j++) {
        int gc = n0 + wn + j * 8 + qc;
        float b0 = __ldg(&bias[gc]);
        float b1 = __ldg(&bias[gc + 1]);
#pragma unroll
        for (int i = 0; i < 4; i++) {
            int gr = m0 + wm + i * 16 + qr;
            float2 v0 = make_float2(acc[i][j][0] + b0, acc[i][j][1] + b1);
            float2 v1 = make_float2(acc[i][j][2] + b0, acc[i][j][3] + b1);
            *(float2*)&Y[(size_t)gr * DMODEL + gc]       = v0;
            *(float2*)&Y[(size_t)(gr + 8) * DMODEL + gc] = v1;
        }
    }
}

// =================================================================
// Flash attention v2 (fp32 SIMT): BQ=128, BK=128, 256 threads,
// 8x8 microtile, conflict-free lane mapping.
// =================================================================
#define BQ 128
#define BK 128
#define QLD 68
#define KLD 132
#define VLD 68
#define PLD 132
#define FA_QS   0
#define FA_KST  (BQ * QLD)                 // 8704
#define FA_VS   (FA_KST + DHEAD * KLD)     // 17152
#define FA_PS   (FA_VS + BK * VLD)         // 25856
#define FA_FLT  (FA_PS + BQ * PLD)         // 42752 floats
#define FA_SMEM (FA_FLT * 4)               // 171008 bytes

__global__ __launch_bounds__(256) void flash2(
    const float* __restrict__ Qp, const float* __restrict__ Kp,
    const float* __restrict__ Vp, float* __restrict__ Out)
{
    extern __shared__ float smf[];
    float* Qs  = smf + FA_QS;
    float* Kst = smf + FA_KST;
    float* Vs  = smf + FA_VS;
    float* Ps  = smf + FA_PS;

    const int qt = blockIdx.x;
    const int h  = blockIdx.y;
    const int b  = blockIdx.z;
    const int tid = threadIdx.x;
    const int tx  = tid & 15;
    const int ty  = tid >> 4;
    const int qrow0 = ty * 8;
    const size_t head_off = (size_t)h * DHEAD;

    const int lr   = tid & 127;     // row for load phases
    const int lhal = tid >> 7;      // 0/1 -> 32-float half of the row

    // ---- load Q tile ----
    {
        const float4* src = (const float4*)&Qp[((size_t)(b * SEQ + qt * BQ + lr)) * DMODEL
                                               + head_off + lhal * 32];
        float4* dst = (float4*)&Qs[lr * QLD + lhal * 32];
#pragma unroll
        for (int c = 0; c < 8; c++) dst[c] = src[c];
    }

    float m_[8], l_[8], acc[8][4];
#pragma unroll
    for (int i = 0; i < 8; i++) {
        m_[i] = -1e30f; l_[i] = 0.0f;
#pragma unroll
        for (int d = 0; d < 4; d++) acc[i][d] = 0.0f;
    }
    __syncthreads();

#pragma unroll 1
    for (int kt = 0; kt < SEQ / BK; kt++) {
        // ---- load K (transposed to d-major) and V ----
        {
            size_t grow = ((size_t)(b * SEQ + kt * BK + lr)) * DMODEL + head_off + lhal * 32;
            const float4* ksrc = (const float4*)&Kp[grow];
#pragma unroll
            for (int c = 0; c < 8; c++) {
                float4 kv = ksrc[c];
                int d = lhal * 32 + c * 4;
                Kst[(d + 0) * KLD + lr] = kv.x;
                Kst[(d + 1) * KLD + lr] = kv.y;
                Kst[(d + 2) * KLD + lr] = kv.z;
                Kst[(d + 3) * KLD + lr] = kv.w;
            }
            const float4* vsrc = (const float4*)&Vp[grow];
            float4* vdst = (float4*)&Vs[lr * VLD + lhal * 32];
#pragma unroll
            for (int c = 0; c < 8; c++) vdst[c] = vsrc[c];
        }
        __syncthreads();

        // ---- S = Q . K^T : 8 rows x (tx*4 .. +3, 64+tx*4 .. +3) ----
        float s[8][8];
#pragma unroll
        for (int i = 0; i < 8; i++)
#pragma unroll
            for (int j = 0; j < 8; j++) s[i][j] = 0.0f;

#pragma unroll 1
        for (int k4 = 0; k4 < DHEAD; k4 += 4) {
            float qa[8][4];
#pragma unroll
            for (int i = 0; i < 8; i++)
                *(float4*)qa[i] = *(const float4*)&Qs[(qrow0 + i) * QLD + k4];
#pragma unroll
            for (int e = 0; e < 4; e++) {
                float kf[8];
                *(float4*)&kf[0] = *(const float4*)&Kst[(k4 + e) * KLD + tx * 4];
                *(float4*)&kf[4] = *(const float4*)&Kst[(k4 + e) * KLD + 64 + tx * 4];
#pragma unroll
                for (int i = 0; i < 8; i++) {
                    float q = qa[i][e];
#pragma unroll
                    for (int j = 0; j < 8; j++)
                        s[i][j] = fmaf(q, kf[j], s[i][j]);
                }
            }
        }

        // ---- online softmax ----
#pragma unroll
        for (int i = 0; i < 8; i++) {
            float mt = s[i][0];
#pragma unroll
            for (int j = 1; j < 8; j++) mt = fmaxf(mt, s[i][j]);
            mt = fmaxf(mt, __shfl_xor_sync(0xffffffffu, mt, 1));
            mt = fmaxf(mt, __shfl_xor_sync(0xffffffffu, mt, 2));
            mt = fmaxf(mt, __shfl_xor_sync(0xffffffffu, mt, 4));
            mt = fmaxf(mt, __shfl_xor_sync(0xffffffffu, mt, 8));
            float mnew = fmaxf(m_[i], mt);
            float corr = __expf(m_[i] - mnew);
            float ls = 0.0f;
#pragma unroll
            for (int j = 0; j < 8; j++) {
                float p = __expf(s[i][j] - mnew);
                s[i][j] = p;
                ls += p;
            }
            ls += __shfl_xor_sync(0xffffffffu, ls, 1);
            ls += __shfl_xor_sync(0xffffffffu, ls, 2);
            ls += __shfl_xor_sync(0xffffffffu, ls, 4);
            ls += __shfl_xor_sync(0xffffffffu, ls, 8);
            l_[i] = l_[i] * corr + ls;
            m_[i] = mnew;
#pragma unroll
            for (int d = 0; d < 4; d++) acc[i][d] *= corr;
            *(float4*)&Ps[(qrow0 + i) * PLD + tx * 4]      = *(float4*)&s[i][0];
            *(float4*)&Ps[(qrow0 + i) * PLD + 64 + tx * 4] = *(float4*)&s[i][4];
        }
        __syncthreads();

        // ---- acc += P . V : 8 rows x 4 d-cols (tx*4..+3) ----
#pragma unroll 1
        for (int j4 = 0; j4 < BK; j4 += 4) {
            float pa[8][4];
#pragma unroll
            for (int i = 0; i < 8; i++)
                *(float4*)pa[i] = *(const float4*)&Ps[(qrow0 + i) * PLD + j4];
#pragma unroll
            for (int e = 0; e < 4; e++) {
                float vf[4];
                *(float4*)vf = *(const float4*)&Vs[(j4 + e) * VLD + tx * 4];
#pragma unroll
                for (int i = 0; i < 8; i++) {
                    float pv = pa[i][e];
#pragma unroll
                    for (int d = 0; d < 4; d++)
                        acc[i][d] = fmaf(pv, vf[d], acc[i][d]);
                }
            }
        }
        __syncthreads();
    }

    // ---- write output ----
#pragma unroll
    for (int i = 0; i < 8; i++) {
        float inv = 1.0f / l_[i];
        float4 o = make_float4(acc[i][0] * inv, acc[i][1] * inv,
                               acc[i][2] * inv, acc[i][3] * inv);
        *(float4*)&Out[((size_t)(b * SEQ + qt * BQ + qrow0 + i)) * DMODEL
                       + head_off + tx * 4] = o;
    }
}

// =================================================================
extern "C" void kernel_launch(void* const* d_in, const int* in_sizes, int n_in,
                              void* d_out, int out_size)
{
    const float* q  = (const float*)d_in[0];
    const float* k  = (const float*)d_in[1];
    const float* v  = (const float*)d_in[2];
    const float* Wq = (const float*)d_in[3];
    const float* bq = (const float*)d_in[4];
    const float* Wk = (const float*)d_in[5];
    const float* bk = (const float*)d_in[6];
    const float* Wv = (const float*)d_in[7];
    const float* bv = (const float*)d_in[8];
    float* out = (float*)d_out;

    float *Qp, *Kp, *Vp;
    __nv_bfloat16 *Ah, *Al, *Wh, *Wl;
    cudaGetSymbolAddress((void**)&Qp, g_Qp);
    cudaGetSymbolAddress((void**)&Kp, g_Kp);
    cudaGetSymbolAddress((void**)&Vp, g_Vp);
    cudaGetSymbolAddress((void**)&Ah, g_Ah);
    cudaGetSymbolAddress((void**)&Al, g_Al);
    cudaGetSymbolAddress((void**)&Wh, g_Wh);
    cudaGetSymbolAddress((void**)&Wl, g_Wl);

    const size_t MD = (size_t)MROWS * DMODEL;     // 6291456
    const size_t WD = (size_t)DMODEL * DMODEL;    // 589824
    const int n4i = (int)(MD / 4);
    const int n4w = (int)(WD / 4);

    const float* xs[3] = {q, k, v};
    const float* ws[3] = {Wq, Wk, Wv};
    const float* bs[3] = {bq, bk, bv};
    float* ys[3] = {Qp, Kp, Vp};

    for (int i = 0; i < 3; i++) {
        split_bf16<<<(n4i + 255) / 256, 256>>>(xs[i], Ah + i * MD, Al + i * MD, n4i);
        split_bf16<<<(n4w + 255) / 256, 256>>>(ws[i], Wh + i * WD, Wl + i * WD, n4w);
    }

    static bool attr_done = false;
    if (!attr_done) {
        cudaFuncSetAttribute(proj_mma, cudaFuncAttributeMaxDynamicSharedMemorySize, PJ_SMEM);
        cudaFuncSetAttribute(flash2, cudaFuncAttributeMaxDynamicSharedMemorySize, FA_SMEM);
        attr_done = true;
    }

    dim3 pgrid(DMODEL / 128, MROWS / 128);   // (6, 64)
    for (int i = 0; i < 3; i++)
        proj_mma<<<pgrid, 256, PJ_SMEM>>>(Ah + i * MD, Al + i * MD,
                                          Wh + i * WD, Wl + i * WD, bs[i], ys[i]);

    dim3 agrid(SEQ / BQ, NHEAD, BS);         // (16, 12, 4)
    flash2<<<agrid, 256, FA_SMEM>>>(Qp, Kp, Vp, out);
}

// round 5
// speedup vs baseline: 4.4969x; 2.8506x over previous
#include <cuda_runtime.h>
#include <cuda_fp16.h>
#include <cuda_bf16.h>
#include <cstdint>

// Problem constants
#define BS      4
#define SEQ     2048
#define DMODEL  768
#define NHEAD   12
#define DHEAD   64
#define MROWS   (BS * SEQ)          // 8192

// ---------------- scratch (no cudaMalloc allowed) ----------------
__device__ __nv_bfloat16 g_Ah[3 * MROWS * DMODEL];   // q,k,v inputs hi (proj A)
__device__ __nv_bfloat16 g_Al[3 * MROWS * DMODEL];   // q,k,v inputs lo
__device__ __nv_bfloat16 g_Wh[3 * DMODEL * DMODEL];  // weights hi
__device__ __nv_bfloat16 g_Wl[3 * DMODEL * DMODEL];  // weights lo
__device__ __half g_Qh[MROWS * DMODEL];              // proj outputs, fp16
__device__ __half g_Ql[MROWS * DMODEL];
__device__ __half g_Kh[MROWS * DMODEL];
__device__ __half g_Kl[MROWS * DMODEL];
__device__ __half g_Vv[MROWS * DMODEL];

// =================================================================
// low-level helpers (family-common PTX: sm_80+ mma/ldmatrix/cp.async)
// =================================================================
__device__ __forceinline__ uint32_t cvta_s(const void* p) {
    return (uint32_t)__cvta_generic_to_shared(p);
}
__device__ __forceinline__ void cp16(uint32_t saddr, const void* gptr) {
    asm volatile("cp.async.ca.shared.global [%0], [%1], 16;" :: "r"(saddr), "l"(gptr));
}
#define CP_COMMIT() asm volatile("cp.async.commit_group;" ::: "memory")
#define CP_WAIT0()  asm volatile("cp.async.wait_group 0;" ::: "memory")
#define CP_WAIT1()  asm volatile("cp.async.wait_group 1;" ::: "memory")

__device__ __forceinline__ void ldm_x4(uint32_t* r, uint32_t saddr) {
    asm volatile("ldmatrix.sync.aligned.m8n8.x4.shared.b16 {%0,%1,%2,%3}, [%4];"
        : "=r"(r[0]), "=r"(r[1]), "=r"(r[2]), "=r"(r[3]) : "r"(saddr));
}
__device__ __forceinline__ void ldm_x4t(uint32_t* r, uint32_t saddr) {
    asm volatile("ldmatrix.sync.aligned.m8n8.x4.trans.shared.b16 {%0,%1,%2,%3}, [%4];"
        : "=r"(r[0]), "=r"(r[1]), "=r"(r[2]), "=r"(r[3]) : "r"(saddr));
}
__device__ __forceinline__ void mma_bf16(float* c, const uint32_t* a, uint32_t b0, uint32_t b1) {
    asm volatile(
        "mma.sync.aligned.m16n8k16.row.col.f32.bf16.bf16.f32 "
        "{%0,%1,%2,%3},{%4,%5,%6,%7},{%8,%9},{%0,%1,%2,%3};"
        : "+f"(c[0]), "+f"(c[1]), "+f"(c[2]), "+f"(c[3])
        : "r"(a[0]), "r"(a[1]), "r"(a[2]), "r"(a[3]), "r"(b0), "r"(b1));
}
__device__ __forceinline__ void mma_f16(float* c, const uint32_t* a, uint32_t b0, uint32_t b1) {
    asm volatile(
        "mma.sync.aligned.m16n8k16.row.col.f32.f16.f16.f32 "
        "{%0,%1,%2,%3},{%4,%5,%6,%7},{%8,%9},{%0,%1,%2,%3};"
        : "+f"(c[0]), "+f"(c[1]), "+f"(c[2]), "+f"(c[3])
        : "r"(a[0]), "r"(a[1]), "r"(a[2]), "r"(a[3]), "r"(b0), "r"(b1));
}
__device__ __forceinline__ uint32_t pk2(float x, float y) {
    __half2 h = __floats2half2_rn(x, y);
    return *(uint32_t*)&h;
}

// =================================================================
// fp32 -> (hi, lo) bf16 split (proj inputs / weights)
// =================================================================
__global__ __launch_bounds__(256) void split_bf16(
    const float* __restrict__ src, __nv_bfloat16* __restrict__ hi,
    __nv_bfloat16* __restrict__ lo, int n4)
{
    int i = blockIdx.x * blockDim.x + threadIdx.x;
    if (i >= n4) return;
    float4 x = ((const float4*)src)[i];
    __nv_bfloat16 h0 = __float2bfloat16(x.x);
    __nv_bfloat16 h1 = __float2bfloat16(x.y);
    __nv_bfloat16 h2 = __float2bfloat16(x.z);
    __nv_bfloat16 h3 = __float2bfloat16(x.w);
    __nv_bfloat16 l0 = __float2bfloat16(x.x - __bfloat162float(h0));
    __nv_bfloat16 l1 = __float2bfloat16(x.y - __bfloat162float(h1));
    __nv_bfloat16 l2 = __float2bfloat16(x.z - __bfloat162float(h2));
    __nv_bfloat16 l3 = __float2bfloat16(x.w - __bfloat162float(h3));
    __nv_bfloat162* hp = (__nv_bfloat162*)hi;
    __nv_bfloat162* lp = (__nv_bfloat162*)lo;
    hp[2 * i]     = __halves2bfloat162(h0, h1);
    hp[2 * i + 1] = __halves2bfloat162(h2, h3);
    lp[2 * i]     = __halves2bfloat162(l0, l1);
    lp[2 * i + 1] = __halves2bfloat162(l2, l3);
}

// =================================================================
// Projection GEMM (mma.sync, split-bf16 3-term): out = fp16 (hi[,lo])
// CTA 128x128, K-chunk 64, cp.async double-buffered.
// =================================================================
#define PJ_STRIDE_B 144                      // 72 halves
#define PJ_TILE_B   (128 * PJ_STRIDE_B)      // 18432
#define PJ_SMEM     (8 * PJ_TILE_B)          // 147456 (2 buffers x 4 tiles)

__global__ __launch_bounds__(256) void proj_mma(
    const __nv_bfloat16* __restrict__ Xh, const __nv_bfloat16* __restrict__ Xl,
    const __nv_bfloat16* __restrict__ Wh, const __nv_bfloat16* __restrict__ Wl,
    const float* __restrict__ bias,
    __half* __restrict__ Oh, __half* __restrict__ Ol, int write_lo)
{
    extern __shared__ __align__(16) char sm[];

    const int K = DMODEL;
    const int tid  = threadIdx.x;
    const int wid  = tid >> 5;
    const int lane = tid & 31;
    const int m0 = blockIdx.y * 128;
    const int n0 = blockIdx.x * 128;
    const int wm = (wid >> 2) * 64;
    const int wn = (wid & 3) * 32;
    const int qr = lane >> 2;
    const int qc = (lane & 3) * 2;

    float acc[4][4][4];
#pragma unroll
    for (int i = 0; i < 4; i++)
#pragma unroll
        for (int j = 0; j < 4; j++)
#pragma unroll
            for (int r = 0; r < 4; r++) acc[i][j][r] = 0.0f;

    // cooperative async load of chunk c into buffer buf
    auto load_chunk = [&](int c, int buf) {
        const int k0 = c * 64;
        char* base = sm + buf * 4 * PJ_TILE_B;
#pragma unroll
        for (int it = 0; it < 4; it++) {
            int idx = it * 256 + tid;
            int row = idx >> 3;
            int c8  = idx & 7;
            uint32_t soff = row * PJ_STRIDE_B + c8 * 16;
            size_t goff = (size_t)(m0 + row) * K + k0 + c8 * 8;
            size_t woff = (size_t)(n0 + row) * K + k0 + c8 * 8;
            cp16(cvta_s(base + soff),                 &Xh[goff]);
            cp16(cvta_s(base + PJ_TILE_B + soff),     &Xl[goff]);
            cp16(cvta_s(base + 2 * PJ_TILE_B + soff), &Wh[woff]);
            cp16(cvta_s(base + 3 * PJ_TILE_B + soff), &Wl[woff]);
        }
    };

    load_chunk(0, 0);
    CP_COMMIT();

    for (int c = 0; c < 12; c++) {
        if (c + 1 < 12) { load_chunk(c + 1, (c + 1) & 1); CP_COMMIT(); }
        if (c + 1 < 12) CP_WAIT1(); else CP_WAIT0();
        __syncthreads();

        char* base = sm + (c & 1) * 4 * PJ_TILE_B;
        char* smAh = base;
        char* smAl = base + PJ_TILE_B;
        char* smBh = base + 2 * PJ_TILE_B;
        char* smBl = base + 3 * PJ_TILE_B;

#pragma unroll
        for (int ks = 0; ks < 4; ks++) {
            const int kb = ks * 16 + qc;
            uint32_t ah[4][4], al[4][4], bh[4][2], bl[4][2];
#pragma unroll
            for (int i = 0; i < 4; i++) {
                int r0 = wm + i * 16 + qr;
                uint32_t o00 = r0 * PJ_STRIDE_B + kb * 2;
                uint32_t o10 = (r0 + 8) * PJ_STRIDE_B + kb * 2;
                ah[i][0] = *(const uint32_t*)(smAh + o00);
                ah[i][1] = *(const uint32_t*)(smAh + o10);
                ah[i][2] = *(const uint32_t*)(smAh + o00 + 16);
                ah[i][3] = *(const uint32_t*)(smAh + o10 + 16);
                al[i][0] = *(const uint32_t*)(smAl + o00);
                al[i][1] = *(const uint32_t*)(smAl + o10);
                al[i][2] = *(const uint32_t*)(smAl + o00 + 16);
                al[i][3] = *(const uint32_t*)(smAl + o10 + 16);
            }
#pragma unroll
            for (int j = 0; j < 4; j++) {
                int r0 = wn + j * 8 + qr;
                uint32_t o0 = r0 * PJ_STRIDE_B + kb * 2;
                bh[j][0] = *(const uint32_t*)(smBh + o0);
                bh[j][1] = *(const uint32_t*)(smBh + o0 + 16);
                bl[j][0] = *(const uint32_t*)(smBl + o0);
                bl[j][1] = *(const uint32_t*)(smBl + o0 + 16);
            }
#pragma unroll
            for (int i = 0; i < 4; i++)
#pragma unroll
                for (int j = 0; j < 4; j++) {
                    mma_bf16(acc[i][j], ah[i], bh[j][0], bh[j][1]);
                    mma_bf16(acc[i][j], ah[i], bl[j][0], bl[j][1]);
                    mma_bf16(acc[i][j], al[i], bh[j][0], bh[j][1]);
                }
        }
        __syncthreads();
    }

    // ---- epilogue: bias, write fp16 hi (and lo) ----
#pragma unroll
    for (int j = 0; j < 4; j++) {
        int gc = n0 + wn + j * 8 + qc;
        float b0 = __ldg(&bias[gc]);
        float b1 = __ldg(&bias[gc + 1]);
#pragma unroll
        for (int i = 0; i < 4; i++) {
            int gr = m0 + wm + i * 16 + qr;
            float y0 = acc[i][j][0] + b0, y1 = acc[i][j][1] + b1;
            float y2 = acc[i][j][2] + b0, y3 = acc[i][j][3] + b1;
            __half h0 = __float2half_rn(y0), h1 = __float2half_rn(y1);
            __half h2 = __float2half_rn(y2), h3 = __float2half_rn(y3);
            *(__half2*)&Oh[(size_t)gr * DMODEL + gc]       = __halves2half2(h0, h1);
            *(__half2*)&Oh[(size_t)(gr + 8) * DMODEL + gc] = __halves2half2(h2, h3);
            if (write_lo) {
                __half l0 = __float2half_rn(y0 - __half2float(h0));
                __half l1 = __float2half_rn(y1 - __half2float(h1));
                __half l2 = __float2half_rn(y2 - __half2float(h2));
                __half l3 = __float2half_rn(y3 - __half2float(h3));
                *(__half2*)&Ol[(size_t)gr * DMODEL + gc]       = __halves2half2(l0, l1);
                *(__half2*)&Ol[(size_t)(gr + 8) * DMODEL + gc] = __halves2half2(l2, l3);
            }
        }
    }
}

// =================================================================
// Flash attention via mma.sync fp16.
// CTA: 128 q-rows x full seq; 8 warps x 16 q-rows. BK=128 keys/iter.
// S = Qh.Kh + Qh.Kl + Ql.Kh (3-term fp16 split); PV single fp16.
// =================================================================
#define FROW   72                   // halves per smem row (144 B)
#define THALF  (128 * FROW)         // halves per 128-row tile
#define FA_SMEM (8 * THALF * 2)     // Qh,Ql + 2 x {Kh,Kl,V} = 147456 B

__global__ __launch_bounds__(256) void flash_mma(
    const __half* __restrict__ Qh, const __half* __restrict__ Ql,
    const __half* __restrict__ Kh, const __half* __restrict__ Kl,
    const __half* __restrict__ Vv, float* __restrict__ Out)
{
    extern __shared__ __align__(16) __half smh[];
    __half* sQh = smh;
    __half* sQl = smh + THALF;
    __half* sKV = smh + 2 * THALF;   // buffers: buf*3*THALF + {Kh,Kl,V}*THALF

    const int qt  = blockIdx.x;
    const int h   = blockIdx.y;
    const int b   = blockIdx.z;
    const int tid  = threadIdx.x;
    const int w    = tid >> 5;
    const int lane = tid & 31;

    const size_t qbase = ((size_t)(b * SEQ + qt * 128)) * DMODEL + h * DHEAD;

    // ---- async-load Q tiles (hi, lo) ----
    {
#pragma unroll
        for (int it = 0; it < 4; it++) {
            int idx = it * 256 + tid;
            int row = idx >> 3;
            int c8  = idx & 7;
            uint32_t soff = row * FROW + c8 * 8;
            size_t goff = qbase + (size_t)row * DMODEL + c8 * 8;
            cp16(cvta_s(sQh + soff), &Qh[goff]);
            cp16(cvta_s(sQl + soff), &Ql[goff]);
        }
    }
    CP_COMMIT();

    auto load_kv = [&](int kt, int buf) {
        __half* base = sKV + buf * 3 * THALF;
        size_t kbase = ((size_t)(b * SEQ + kt * 128)) * DMODEL + h * DHEAD;
#pragma unroll
        for (int it = 0; it < 4; it++) {
            int idx = it * 256 + tid;
            int row = idx >> 3;
            int c8  = idx & 7;
            uint32_t soff = row * FROW + c8 * 8;
            size_t goff = kbase + (size_t)row * DMODEL + c8 * 8;
            cp16(cvta_s(base + soff),             &Kh[goff]);
            cp16(cvta_s(base + THALF + soff),     &Kl[goff]);
            cp16(cvta_s(base + 2 * THALF + soff), &Vv[goff]);
        }
    };

    load_kv(0, 0);
    CP_COMMIT();

    // ---- wait for Q, read Q fragments (held for the whole kernel) ----
    CP_WAIT1();
    __syncthreads();

    const int fr = (lane & 7) + 8 * ((lane >> 3) & 1);   // ldmatrix row-in-16
    const int fc = 8 * ((lane >> 4) & 1);                // ldmatrix col half

    uint32_t qhF[4][4], qlF[4][4];
    {
        int qrow = 16 * w + fr;
#pragma unroll
        for (int kc = 0; kc < 4; kc++) {
            ldm_x4(qhF[kc], cvta_s(sQh + qrow * FROW + kc * 16 + fc));
            ldm_x4(qlF[kc], cvta_s(sQl + qrow * FROW + kc * 16 + fc));
        }
    }

    float m0 = -1e30f, m1 = -1e30f, l0 = 0.0f, l1 = 0.0f;
    float O[8][4];
#pragma unroll
    for (int dt = 0; dt < 8; dt++)
#pragma unroll
        for (int r = 0; r < 4; r++) O[dt][r] = 0.0f;

#pragma unroll 1
    for (int kt = 0; kt < SEQ / 128; kt++) {
        if (kt + 1 < SEQ / 128) { load_kv(kt + 1, (kt + 1) & 1); CP_COMMIT(); }
        if (kt + 1 < SEQ / 128) CP_WAIT1(); else CP_WAIT0();
        __syncthreads();

        __half* base = sKV + (kt & 1) * 3 * THALF;
        __half* bKh = base;
        __half* bKl = base + THALF;
        __half* bV  = base + 2 * THALF;

        // ---- S = Q.K^T (3-term) : 16 n-tiles of 8 keys ----
        float S[16][4];
#pragma unroll
        for (int nt = 0; nt < 16; nt++)
#pragma unroll
            for (int r = 0; r < 4; r++) S[nt][r] = 0.0f;

#pragma unroll
        for (int nt2 = 0; nt2 < 8; nt2++) {
            int krow = nt2 * 16 + fr;
#pragma unroll
            for (int kc = 0; kc < 4; kc++) {
                uint32_t bh[4], bl[4];
                ldm_x4(bh, cvta_s(bKh + krow * FROW + kc * 16 + fc));
                ldm_x4(bl, cvta_s(bKl + krow * FROW + kc * 16 + fc));
                mma_f16(S[2 * nt2],     qhF[kc], bh[0], bh[2]);
                mma_f16(S[2 * nt2],     qhF[kc], bl[0], bl[2]);
                mma_f16(S[2 * nt2],     qlF[kc], bh[0], bh[2]);
                mma_f16(S[2 * nt2 + 1], qhF[kc], bh[1], bh[3]);
                mma_f16(S[2 * nt2 + 1], qhF[kc], bl[1], bl[3]);
                mma_f16(S[2 * nt2 + 1], qlF[kc], bh[1], bh[3]);
            }
        }

        // ---- online softmax on fragments (rows qr, qr+8) ----
        float mx0 = S[0][0], mx1 = S[0][2];
#pragma unroll
        for (int nt = 0; nt < 16; nt++) {
            mx0 = fmaxf(mx0, fmaxf(S[nt][0], S[nt][1]));
            mx1 = fmaxf(mx1, fmaxf(S[nt][2], S[nt][3]));
        }
        mx0 = fmaxf(mx0, __shfl_xor_sync(0xffffffffu, mx0, 1));
        mx0 = fmaxf(mx0, __shfl_xor_sync(0xffffffffu, mx0, 2));
        mx1 = fmaxf(mx1, __shfl_xor_sync(0xffffffffu, mx1, 1));
        mx1 = fmaxf(mx1, __shfl_xor_sync(0xffffffffu, mx1, 2));
        float mn0 = fmaxf(m0, mx0), mn1 = fmaxf(m1, mx1);
        float c0 = __expf(m0 - mn0), c1 = __expf(m1 - mn1);
        float s0 = 0.0f, s1 = 0.0f;
#pragma unroll
        for (int nt = 0; nt < 16; nt++) {
            S[nt][0] = __expf(S[nt][0] - mn0); s0 += S[nt][0];
            S[nt][1] = __expf(S[nt][1] - mn0); s0 += S[nt][1];
            S[nt][2] = __expf(S[nt][2] - mn1); s1 += S[nt][2];
            S[nt][3] = __expf(S[nt][3] - mn1); s1 += S[nt][3];
        }
        s0 += __shfl_xor_sync(0xffffffffu, s0, 1);
        s0 += __shfl_xor_sync(0xffffffffu, s0, 2);
        s1 += __shfl_xor_sync(0xffffffffu, s1, 1);
        s1 += __shfl_xor_sync(0xffffffffu, s1, 2);
        l0 = l0 * c0 + s0; l1 = l1 * c1 + s1;
        m0 = mn0; m1 = mn1;
#pragma unroll
        for (int dt = 0; dt < 8; dt++) {
            O[dt][0] *= c0; O[dt][1] *= c0;
            O[dt][2] *= c1; O[dt][3] *= c1;
        }

        // ---- O += P.V : P fragments from S regs, V via ldmatrix.trans ----
#pragma unroll
        for (int kc = 0; kc < 8; kc++) {
            uint32_t a[4];
            a[0] = pk2(S[2 * kc][0],     S[2 * kc][1]);
            a[1] = pk2(S[2 * kc][2],     S[2 * kc][3]);
            a[2] = pk2(S[2 * kc + 1][0], S[2 * kc + 1][1]);
            a[3] = pk2(S[2 * kc + 1][2], S[2 * kc + 1][3]);
            int vrow = kc * 16 + fr;
#pragma unroll
            for (int dt2 = 0; dt2 < 4; dt2++) {
                uint32_t r[4];
                ldm_x4t(r, cvta_s(bV + vrow * FROW + dt2 * 16 + fc));
                mma_f16(O[2 * dt2],     a, r[0], r[1]);
                mma_f16(O[2 * dt2 + 1], a, r[2], r[3]);
            }
        }
        __syncthreads();
    }

    // ---- write output ----
    float il0 = 1.0f / l0, il1 = 1.0f / l1;
    int row0 = b * SEQ + qt * 128 + 16 * w + (lane >> 2);
    int dcol = h * DHEAD + 2 * (lane & 3);
#pragma unroll
    for (int dt = 0; dt < 8; dt++) {
        *(float2*)&Out[(size_t)row0 * DMODEL + dcol + dt * 8] =
            make_float2(O[dt][0] * il0, O[dt][1] * il0);
        *(float2*)&Out[(size_t)(row0 + 8) * DMODEL + dcol + dt * 8] =
            make_float2(O[dt][2] * il1, O[dt][3] * il1);
    }
}

// =================================================================
extern "C" void kernel_launch(void* const* d_in, const int* in_sizes, int n_in,
                              void* d_out, int out_size)
{
    const float* q  = (const float*)d_in[0];
    const float* k  = (const float*)d_in[1];
    const float* v  = (const float*)d_in[2];
    const float* Wq = (const float*)d_in[3];
    const float* bq = (const float*)d_in[4];
    const float* Wk = (const float*)d_in[5];
    const float* bk = (const float*)d_in[6];
    const float* Wv = (const float*)d_in[7];
    const float* bv = (const float*)d_in[8];
    float* out = (float*)d_out;

    __nv_bfloat16 *Ah, *Al, *Wh, *Wl;
    __half *Qh, *Ql, *Kh, *Kl, *Vv;
    cudaGetSymbolAddress((void**)&Ah, g_Ah);
    cudaGetSymbolAddress((void**)&Al, g_Al);
    cudaGetSymbolAddress((void**)&Wh, g_Wh);
    cudaGetSymbolAddress((void**)&Wl, g_Wl);
    cudaGetSymbolAddress((void**)&Qh, g_Qh);
    cudaGetSymbolAddress((void**)&Ql, g_Ql);
    cudaGetSymbolAddress((void**)&Kh, g_Kh);
    cudaGetSymbolAddress((void**)&Kl, g_Kl);
    cudaGetSymbolAddress((void**)&Vv, g_Vv);

    const size_t MD = (size_t)MROWS * DMODEL;
    const size_t WD = (size_t)DMODEL * DMODEL;
    const int n4i = (int)(MD / 4);
    const int n4w = (int)(WD / 4);

    const float* xs[3] = {q, k, v};
    const float* ws[3] = {Wq, Wk, Wv};
    const float* bs[3] = {bq, bk, bv};

    for (int i = 0; i < 3; i++) {
        split_bf16<<<(n4i + 255) / 256, 256>>>(xs[i], Ah + i * MD, Al + i * MD, n4i);
        split_bf16<<<(n4w + 255) / 256, 256>>>(ws[i], Wh + i * WD, Wl + i * WD, n4w);
    }

    cudaFuncSetAttribute(proj_mma, cudaFuncAttributeMaxDynamicSharedMemorySize, PJ_SMEM);
    cudaFuncSetAttribute(flash_mma, cudaFuncAttributeMaxDynamicSharedMemorySize, FA_SMEM);

    dim3 pgrid(DMODEL / 128, MROWS / 128);   // (6, 64)
    proj_mma<<<pgrid, 256, PJ_SMEM>>>(Ah + 0 * MD, Al + 0 * MD, Wh + 0 * WD, Wl + 0 * WD,
                                      bs[0], Qh, Ql, 1);
    proj_mma<<<pgrid, 256, PJ_SMEM>>>(Ah + 1 * MD, Al + 1 * MD, Wh + 1 * WD, Wl + 1 * WD,
                                      bs[1], Kh, Kl, 1);
    proj_mma<<<pgrid, 256, PJ_SMEM>>>(Ah + 2 * MD, Al + 2 * MD, Wh + 2 * WD, Wl + 2 * WD,
                                      bs[2], Vv, Ql /*unused*/, 0);

    dim3 agrid(SEQ / 128, NHEAD, BS);        // (16, 12, 4)
    flash_mma<<<agrid, 256, FA_SMEM>>>(Qh, Ql, Kh, Kl, Vv, out);
}